// round 1
// baseline (speedup 1.0000x reference)
#include <cuda_runtime.h>
#include <cuda_bf16.h>

// WaveletSparsityPrior: 3-level Haar DWT sparsity loss, fully fused.
// Key fact: 3-level Haar is block-diagonal on 8x8 patches -> one streaming pass.

#define H 1024
#define W 1024
#define B 64

__device__ double g_acc;

__global__ void zero_acc_kernel() {
    g_acc = 0.0;
}

__global__ void finalize_kernel(float* out) {
    out[0] = (float)g_acc;
}

__device__ __forceinline__ float bandterm(float v, float thr) {
    return fminf(fabsf(v), thr);
}

__global__ __launch_bounds__(256) void wavelet_loss_kernel(const float* __restrict__ pred) {
    // Each thread: one 8x8 patch. 128x128 patches per image, 64 images.
    const unsigned tid = blockIdx.x * 256u + threadIdx.x;
    const unsigned img = tid >> 14;            // / 16384
    const unsigned p   = tid & 16383u;
    const unsigned pr  = p >> 7;               // patch row 0..127
    const unsigned pc  = p & 127u;             // patch col 0..127

    const float* base = pred + (size_t)img * (H * W) + (size_t)pr * 8 * W + (size_t)pc * 8;

    const float BASE_THR = 50.0f / 255.0f;
    const float T1 = BASE_THR * 0.25f;   // level 1 (finest), level_idx=3
    const float T2 = BASE_THR * 0.5f;    // level 2, level_idx=2
    const float T3 = BASE_THR;           // level 3, level_idx=1

    float s1 = 0.f, s2 = 0.f, s3 = 0.f;
    float ll1[4][4];

    // ---- Level 1: 8x8 -> 4x4 LL + band sums ----
    #pragma unroll
    for (int i = 0; i < 4; i++) {
        const float* r0 = base + (size_t)(2 * i) * W;
        const float* r1 = r0 + W;
        float4 a0 = *(const float4*)(r0);
        float4 a1 = *(const float4*)(r0 + 4);
        float4 b0 = *(const float4*)(r1);
        float4 b1 = *(const float4*)(r1 + 4);
        float top[8] = {a0.x, a0.y, a0.z, a0.w, a1.x, a1.y, a1.z, a1.w};
        float bot[8] = {b0.x, b0.y, b0.z, b0.w, b1.x, b1.y, b1.z, b1.w};
        #pragma unroll
        for (int j = 0; j < 4; j++) {
            float a = top[2 * j],     bb = bot[2 * j];
            float c = top[2 * j + 1], d  = bot[2 * j + 1];
            float s = a + bb, t = bb - a;   // vertical lo/hi, left col
            float u = c + d,  v = d - c;    // vertical lo/hi, right col
            float ll = 0.5f * (s + u);
            float lh = 0.5f * (u - s);
            float hl = 0.5f * (t + v);
            float hh = 0.5f * (v - t);
            s1 += bandterm(lh, T1) + bandterm(hl, T1) + bandterm(hh, T1);
            ll1[i][j] = ll;
        }
    }

    // ---- Level 2: 4x4 -> 2x2 LL + band sums ----
    float ll2[2][2];
    #pragma unroll
    for (int i = 0; i < 2; i++) {
        #pragma unroll
        for (int j = 0; j < 2; j++) {
            float a = ll1[2 * i][2 * j],     bb = ll1[2 * i + 1][2 * j];
            float c = ll1[2 * i][2 * j + 1], d  = ll1[2 * i + 1][2 * j + 1];
            float s = a + bb, t = bb - a;
            float u = c + d,  v = d - c;
            float ll = 0.5f * (s + u);
            float lh = 0.5f * (u - s);
            float hl = 0.5f * (t + v);
            float hh = 0.5f * (v - t);
            s2 += bandterm(lh, T2) + bandterm(hl, T2) + bandterm(hh, T2);
            ll2[i][j] = ll;
        }
    }

    // ---- Level 3: 2x2 -> band sums ----
    {
        float a = ll2[0][0], bb = ll2[1][0];
        float c = ll2[0][1], d  = ll2[1][1];
        float s = a + bb, t = bb - a;
        float u = c + d,  v = d - c;
        float lh = 0.5f * (u - s);
        float hl = 0.5f * (t + v);
        float hh = 0.5f * (v - t);
        s3 += bandterm(lh, T3) + bandterm(hl, T3) + bandterm(hh, T3);
    }

    // Per-level scale: weight_j / (3 * N_j)
    const double C1 = (1.0 / 3.0) / (3.0 * 64.0 * 512.0 * 512.0);
    const double C2 = (1.0 / 2.0) / (3.0 * 64.0 * 256.0 * 256.0);
    const double C3 = (1.0      ) / (3.0 * 64.0 * 128.0 * 128.0);

    double part = (double)s1 * C1 + (double)s2 * C2 + (double)s3 * C3;

    // Warp reduce (double)
    #pragma unroll
    for (int off = 16; off > 0; off >>= 1)
        part += __shfl_down_sync(0xffffffffu, part, off);

    __shared__ double warpsum[8];
    const int lane = threadIdx.x & 31;
    const int wid  = threadIdx.x >> 5;
    if (lane == 0) warpsum[wid] = part;
    __syncthreads();
    if (threadIdx.x == 0) {
        double t = 0.0;
        #pragma unroll
        for (int i = 0; i < 8; i++) t += warpsum[i];
        atomicAdd(&g_acc, t);
    }
}

extern "C" void kernel_launch(void* const* d_in, const int* in_sizes, int n_in,
                              void* d_out, int out_size) {
    const float* pred = (const float*)d_in[0];
    float* out = (float*)d_out;

    zero_acc_kernel<<<1, 1>>>();
    // 64 images * 128*128 patches = 1,048,576 threads = 4096 blocks of 256
    wavelet_loss_kernel<<<4096, 256>>>(pred);
    finalize_kernel<<<1, 1>>>(out);
}

// round 3
// speedup vs baseline: 1.0043x; 1.0043x over previous
#include <cuda_runtime.h>
#include <cuda_bf16.h>

// WaveletSparsityPrior: 3-level Haar DWT sparsity loss, fully fused into ONE kernel.
// 3-level Haar is block-diagonal on 8x8 patches -> one streaming pass.
// Reduction finalized by last-block-done pattern (self-resetting, graph-replay safe).

#define H 1024
#define W 1024
#define B 64
#define NBLOCKS 4096

__device__ double g_acc;            // zero-initialized at module load; reset each run
__device__ unsigned g_count;        // likewise

__device__ __forceinline__ float bandterm(float v, float thr) {
    return fminf(fabsf(v), thr);
}

__global__ __launch_bounds__(256) void wavelet_loss_kernel(const float* __restrict__ pred,
                                                           float* __restrict__ out) {
    // Each thread: one 8x8 patch. 128x128 patches per image, 64 images.
    const unsigned tid = blockIdx.x * 256u + threadIdx.x;
    const unsigned img = tid >> 14;            // / 16384
    const unsigned p   = tid & 16383u;
    const unsigned pr  = p >> 7;               // patch row 0..127
    const unsigned pc  = p & 127u;             // patch col 0..127

    const float* base = pred + (size_t)img * (H * W) + (size_t)pr * 8 * W + (size_t)pc * 8;

    const float BASE_THR = 50.0f / 255.0f;
    const float T1 = BASE_THR * 0.25f;   // level 1 (finest), level_idx=3
    const float T2 = BASE_THR * 0.5f;    // level 2, level_idx=2
    const float T3 = BASE_THR;           // level 3, level_idx=1

    float s1 = 0.f, s2 = 0.f, s3 = 0.f;
    float ll1[4][4];

    // ---- Level 1: 8x8 -> 4x4 LL + band sums ----
    #pragma unroll
    for (int i = 0; i < 4; i++) {
        const float* r0 = base + (size_t)(2 * i) * W;
        const float* r1 = r0 + W;
        float4 a0 = *(const float4*)(r0);
        float4 a1 = *(const float4*)(r0 + 4);
        float4 b0 = *(const float4*)(r1);
        float4 b1 = *(const float4*)(r1 + 4);
        float top[8] = {a0.x, a0.y, a0.z, a0.w, a1.x, a1.y, a1.z, a1.w};
        float bot[8] = {b0.x, b0.y, b0.z, b0.w, b1.x, b1.y, b1.z, b1.w};
        #pragma unroll
        for (int j = 0; j < 4; j++) {
            float a = top[2 * j],     bb = bot[2 * j];
            float c = top[2 * j + 1], d  = bot[2 * j + 1];
            float s = a + bb, t = bb - a;   // vertical lo/hi, left col
            float u = c + d,  v = d - c;    // vertical lo/hi, right col
            float ll = 0.5f * (s + u);
            float lh = 0.5f * (u - s);
            float hl = 0.5f * (t + v);
            float hh = 0.5f * (v - t);
            s1 += bandterm(lh, T1) + bandterm(hl, T1) + bandterm(hh, T1);
            ll1[i][j] = ll;
        }
    }

    // ---- Level 2: 4x4 -> 2x2 LL + band sums ----
    float ll2[2][2];
    #pragma unroll
    for (int i = 0; i < 2; i++) {
        #pragma unroll
        for (int j = 0; j < 2; j++) {
            float a = ll1[2 * i][2 * j],     bb = ll1[2 * i + 1][2 * j];
            float c = ll1[2 * i][2 * j + 1], d  = ll1[2 * i + 1][2 * j + 1];
            float s = a + bb, t = bb - a;
            float u = c + d,  v = d - c;
            float ll = 0.5f * (s + u);
            float lh = 0.5f * (u - s);
            float hl = 0.5f * (t + v);
            float hh = 0.5f * (v - t);
            s2 += bandterm(lh, T2) + bandterm(hl, T2) + bandterm(hh, T2);
            ll2[i][j] = ll;
        }
    }

    // ---- Level 3: 2x2 -> band sums ----
    {
        float a = ll2[0][0], bb = ll2[1][0];
        float c = ll2[0][1], d  = ll2[1][1];
        float s = a + bb, t = bb - a;
        float u = c + d,  v = d - c;
        float lh = 0.5f * (u - s);
        float hl = 0.5f * (t + v);
        float hh = 0.5f * (v - t);
        s3 += bandterm(lh, T3) + bandterm(hl, T3) + bandterm(hh, T3);
    }

    // Per-level scale: weight_j / (3 * N_j)
    const double C1 = (1.0 / 3.0) / (3.0 * 64.0 * 512.0 * 512.0);
    const double C2 = (1.0 / 2.0) / (3.0 * 64.0 * 256.0 * 256.0);
    const double C3 = (1.0      ) / (3.0 * 64.0 * 128.0 * 128.0);

    double part = (double)s1 * C1 + (double)s2 * C2 + (double)s3 * C3;

    // Warp reduce (double)
    #pragma unroll
    for (int off = 16; off > 0; off >>= 1)
        part += __shfl_down_sync(0xffffffffu, part, off);

    __shared__ double warpsum[8];
    const int lane = threadIdx.x & 31;
    const int wid  = threadIdx.x >> 5;
    if (lane == 0) warpsum[wid] = part;
    __syncthreads();

    if (threadIdx.x == 0) {
        double t = 0.0;
        #pragma unroll
        for (int i = 0; i < 8; i++) t += warpsum[i];
        atomicAdd(&g_acc, t);
        __threadfence();
        unsigned prev = atomicAdd(&g_count, 1u);
        if (prev == NBLOCKS - 1u) {
            // Last block: atomically read+reset the accumulator (atomic read
            // guarantees we see all prior L2 atomics), write output, reset counter.
            unsigned long long bits =
                atomicExch((unsigned long long*)&g_acc, 0ull);
            out[0] = (float)__longlong_as_double((long long)bits);
            atomicExch(&g_count, 0u);
        }
    }
}

extern "C" void kernel_launch(void* const* d_in, const int* in_sizes, int n_in,
                              void* d_out, int out_size) {
    const float* pred = (const float*)d_in[0];
    float* out = (float*)d_out;

    // 64 images * 128*128 patches = 1,048,576 threads = 4096 blocks of 256
    wavelet_loss_kernel<<<NBLOCKS, 256>>>(pred, out);
}